// round 3
// baseline (speedup 1.0000x reference)
#include <cuda_runtime.h>
#include <cuda_bf16.h>
#include <cstdint>

#define MAX_NODES 50048
#define MAX_EDGES 800000
#define IN_DIM    128
#define OUT_DIM   64
#define LEAKY     0.01f
#define SCAN_BLK  1024
#define MAX_PARTS ((MAX_NODES + SCAN_BLK - 1) / SCAN_BLK)

// ---------------- scratch (device globals; zero-initialized at load) -------
__device__ float g_z[MAX_NODES * OUT_DIM];   // projected features
__device__ float g_azs[MAX_NODES];           // z . a[:64]
__device__ float g_azd[MAX_NODES];           // z . a[64:]
__device__ int   g_cnt[MAX_NODES];           // per-dst degree   (re-zeroed by scatter)
__device__ int   g_off[MAX_NODES];           // block-exclusive offsets
__device__ int   g_cursor[MAX_NODES];        // fill cursors     (re-zeroed by scatter)
__device__ int   g_part[MAX_PARTS];          // scan block sums
__device__ int   g_partoff[MAX_PARTS];       // scanned block offsets
__device__ int2  g_sw[MAX_EDGES];            // CSR slots: (src, exp(e) bits)
__device__ int   g_scan_done;                // last-block detector (self-resetting)

// ---------------- packed f32x2 helpers --------------------------------------
__device__ __forceinline__ unsigned long long pack2(float lo, float hi) {
    unsigned long long r;
    asm("mov.b64 %0, {%1, %2};" : "=l"(r) : "f"(lo), "f"(hi));
    return r;
}
__device__ __forceinline__ void ffma2(unsigned long long& d,
                                      unsigned long long a,
                                      unsigned long long b) {
    asm("fma.rn.f32x2 %0, %1, %2, %0;" : "+l"(d) : "l"(a), "l"(b));
}
__device__ __forceinline__ float2 unpack2(unsigned long long v) {
    float lo, hi;
    asm("mov.b64 {%0, %1}, %2;" : "=f"(lo), "=f"(hi) : "l"(v));
    return make_float2(lo, hi);
}

// ---------------- kernel 1: projection (FFMA2) + degree histogram -----------
__global__ void __launch_bounds__(128)
proj_count_kernel(const float* __restrict__ feat,
                  const float* __restrict__ W,
                  const float* __restrict__ a,
                  const int* __restrict__ dst,
                  int n_nodes, int n_edges, int proj_blocks) {
    int tid = threadIdx.x;

    if ((int)blockIdx.x >= proj_blocks) {
        // -------- degree count blocks: 4 edges per thread via int4 ----------
        int t4 = ((int)blockIdx.x - proj_blocks) * 128 + tid;
        int base = t4 * 4;
        if (base + 3 < n_edges) {
            int4 d4 = reinterpret_cast<const int4*>(dst)[t4];
            atomicAdd(&g_cnt[d4.x], 1);
            atomicAdd(&g_cnt[d4.y], 1);
            atomicAdd(&g_cnt[d4.z], 1);
            atomicAdd(&g_cnt[d4.w], 1);
        } else {
            for (int t = base; t < n_edges; t++)
                atomicAdd(&g_cnt[dst[t]], 1);
        }
        return;
    }

    // -------- projection blocks ---------------------------------------------
    __shared__ unsigned long long Ws2[IN_DIM * OUT_DIM / 2];  // 32 KB, (k, jpair)
    __shared__ float as[2 * OUT_DIM];

    const float4* W4 = reinterpret_cast<const float4*>(W);
    for (int i = tid; i < IN_DIM * OUT_DIM / 4; i += 128) {
        float4 w = W4[i];
        Ws2[i * 2]     = pack2(w.x, w.y);
        Ws2[i * 2 + 1] = pack2(w.z, w.w);
    }
    if (tid < 2 * OUT_DIM) as[tid] = a[tid];
    __syncthreads();

    int node = blockIdx.x * 128 + tid;
    if (node >= n_nodes) return;

    unsigned long long acc2[32];
#pragma unroll
    for (int j = 0; j < 32; j++) acc2[j] = 0ull;   // (0.f, 0.f)

    const float4* f4 = reinterpret_cast<const float4*>(feat + (size_t)node * IN_DIM);
    for (int k4 = 0; k4 < IN_DIM / 4; k4++) {
        float4 f = f4[k4];
        unsigned long long fx = pack2(f.x, f.x);
        unsigned long long fy = pack2(f.y, f.y);
        unsigned long long fz = pack2(f.z, f.z);
        unsigned long long fw = pack2(f.w, f.w);
        int kb = k4 * 4;
#pragma unroll
        for (int j = 0; j < 32; j++) {
            ffma2(acc2[j], fx, Ws2[(kb + 0) * 32 + j]);
            ffma2(acc2[j], fy, Ws2[(kb + 1) * 32 + j]);
            ffma2(acc2[j], fz, Ws2[(kb + 2) * 32 + j]);
            ffma2(acc2[j], fw, Ws2[(kb + 3) * 32 + j]);
        }
    }

    float s0 = 0.f, s1 = 0.f;
#pragma unroll
    for (int j = 0; j < 32; j++) {
        float2 v = unpack2(acc2[j]);
        s0 += v.x * as[2 * j]           + v.y * as[2 * j + 1];
        s1 += v.x * as[OUT_DIM + 2 * j] + v.y * as[OUT_DIM + 2 * j + 1];
    }
    g_azs[node] = s0;
    g_azd[node] = s1;

    unsigned long long* zo =
        reinterpret_cast<unsigned long long*>(g_z + (size_t)node * OUT_DIM);
#pragma unroll
    for (int j = 0; j < 32; j++) zo[j] = acc2[j];
}

// ---------------- kernel 2: scan (block scan + last-block part scan) --------
__global__ void __launch_bounds__(SCAN_BLK)
scan_kernel(int n, int nparts) {
    int tid = threadIdx.x;
    int i = blockIdx.x * SCAN_BLK + tid;
    int v = (i < n) ? g_cnt[i] : 0;

    int x = v;
#pragma unroll
    for (int o = 1; o < 32; o <<= 1) {
        int y = __shfl_up_sync(0xffffffffu, x, o);
        if ((tid & 31) >= o) x += y;
    }
    __shared__ int wsum[32];
    if ((tid & 31) == 31) wsum[tid >> 5] = x;
    __syncthreads();
    if (tid < 32) {
        int w = wsum[tid];
#pragma unroll
        for (int o = 1; o < 32; o <<= 1) {
            int y = __shfl_up_sync(0xffffffffu, w, o);
            if (tid >= o) w += y;
        }
        wsum[tid] = w;
    }
    __syncthreads();
    int warpoff = (tid >= 32) ? wsum[(tid >> 5) - 1] : 0;
    int incl = x + warpoff;
    if (i < n) g_off[i] = incl - v;
    if (tid == SCAN_BLK - 1) g_part[blockIdx.x] = incl;

    // last-done block scans the 49 block sums (two-warp-width, one warp)
    __shared__ int s_last;
    __threadfence();
    if (tid == 0) {
        int d = atomicAdd(&g_scan_done, 1);
        s_last = (d == (int)gridDim.x - 1) ? 1 : 0;
    }
    __syncthreads();
    if (s_last) {
        __threadfence();
        if (tid < 32) {
            int v0 = (tid < nparts) ? g_part[tid] : 0;
            int v1 = (tid + 32 < nparts) ? g_part[tid + 32] : 0;
            int x0 = v0;
#pragma unroll
            for (int o = 1; o < 32; o <<= 1) {
                int y = __shfl_up_sync(0xffffffffu, x0, o);
                if (tid >= o) x0 += y;
            }
            int tot0 = __shfl_sync(0xffffffffu, x0, 31);
            int x1 = v1;
#pragma unroll
            for (int o = 1; o < 32; o <<= 1) {
                int y = __shfl_up_sync(0xffffffffu, x1, o);
                if (tid >= o) x1 += y;
            }
            if (tid < nparts) g_partoff[tid] = x0 - v0;
            if (tid + 32 < nparts) g_partoff[tid + 32] = tot0 + x1 - v1;
        }
        if (tid == 0) g_scan_done = 0;   // reset for next replay
    }
}

// ---------------- kernel 3: edge weights + CSR fill --------------------------
__global__ void __launch_bounds__(256)
fill_kernel(const int* __restrict__ src,
            const int* __restrict__ dst,
            int n_edges) {
    int t = blockIdx.x * 256 + threadIdx.x;
    if (t >= n_edges) return;
    int s = src[t], d = dst[t];
    float e = g_azs[s] + g_azd[d];
    e = (e > 0.f) ? e : LEAKY * e;
    float w = __expf(e);   // max-shift dropped: e bounded (~|e|<6), exp safe
    int pos = g_off[d] + g_partoff[d >> 10] + atomicAdd(&g_cursor[d], 1);
    g_sw[pos] = make_int2(s, __float_as_int(w));
}

// ---------------- kernel 4: one warp per destination node --------------------
__global__ void __launch_bounds__(256)
scatter_kernel(float* __restrict__ h, int n_nodes) {
    int warp_id = (blockIdx.x * 256 + threadIdx.x) >> 5;
    int lane = threadIdx.x & 31;
    if (warp_id >= n_nodes) return;
    int node = warp_id;

    int start = g_off[node] + g_partoff[node >> 10];
    int cnt = g_cnt[node];

    const unsigned long long* z2 =
        reinterpret_cast<const unsigned long long*>(g_z);

    unsigned long long acc = 0ull;
    float wsum = 0.f;

    for (int base = 0; base < cnt; base += 32) {
        int idx = base + lane;
        int2 sw = (idx < cnt) ? g_sw[start + idx] : make_int2(0, 0);
        int rem = cnt - base;
        if (rem >= 32) {
#pragma unroll
            for (int j = 0; j < 32; j++) {
                int ss = __shfl_sync(0xffffffffu, sw.x, j);
                float ww = __int_as_float(__shfl_sync(0xffffffffu, sw.y, j));
                wsum += ww;
                ffma2(acc, pack2(ww, ww), z2[(size_t)ss * 32 + lane]);
            }
        } else {
            for (int j = 0; j < rem; j++) {
                int ss = __shfl_sync(0xffffffffu, sw.x, j);
                float ww = __int_as_float(__shfl_sync(0xffffffffu, sw.y, j));
                wsum += ww;
                ffma2(acc, pack2(ww, ww), z2[(size_t)ss * 32 + lane]);
            }
        }
    }

    float inv = (cnt > 0) ? 1.f / wsum : 0.f;
    float2 v = unpack2(acc);
    float2* out = reinterpret_cast<float2*>(h + (size_t)node * OUT_DIM);
    out[lane] = make_float2(v.x * inv, v.y * inv);

    // restore invariant for next launch/replay
    if (lane == 0) {
        g_cnt[node] = 0;
        g_cursor[node] = 0;
    }
}

// ---------------- launch ------------------------------------------------------
extern "C" void kernel_launch(void* const* d_in, const int* in_sizes, int n_in,
                              void* d_out, int out_size) {
    const float* feat = (const float*)d_in[0];
    const int*   src  = (const int*)  d_in[1];
    const int*   dst  = (const int*)  d_in[2];
    const float* W    = (const float*)d_in[3];
    const float* a    = (const float*)d_in[4];
    float* h = (float*)d_out;

    int n_nodes = in_sizes[0] / IN_DIM;
    int n_edges = in_sizes[1];
    int nparts = (n_nodes + SCAN_BLK - 1) / SCAN_BLK;

    int proj_blocks  = (n_nodes + 127) / 128;
    int count_blocks = (n_edges + 511) / 512;   // 4 edges/thread
    proj_count_kernel<<<proj_blocks + count_blocks, 128>>>(
        feat, W, a, dst, n_nodes, n_edges, proj_blocks);

    scan_kernel<<<nparts, SCAN_BLK>>>(n_nodes, nparts);

    fill_kernel<<<(n_edges + 255) / 256, 256>>>(src, dst, n_edges);

    {
        int warps_per_block = 256 / 32;
        int blocks = (n_nodes + warps_per_block - 1) / warps_per_block;
        scatter_kernel<<<blocks, 256>>>(h, n_nodes);
    }
}

// round 4
// speedup vs baseline: 1.0790x; 1.0790x over previous
#include <cuda_runtime.h>
#include <cuda_bf16.h>
#include <cstdint>

#define MAX_NODES 50048
#define MAX_EDGES 800000
#define IN_DIM    128
#define OUT_DIM   64
#define LEAKY     0.01f
#define SCAN_BLK  1024
#define MAX_PARTS ((MAX_NODES + SCAN_BLK - 1) / SCAN_BLK)

typedef unsigned long long ull;

// ---------------- scratch (device globals; zero-initialized at load) -------
__device__ float g_z[MAX_NODES * OUT_DIM];   // projected features
__device__ float g_azs[MAX_NODES];           // z . a[:64]
__device__ float g_azd[MAX_NODES];           // z . a[64:]
__device__ int   g_cnt[MAX_NODES];           // per-dst degree   (re-zeroed by scatter)
__device__ int   g_off[MAX_NODES];           // block-exclusive offsets
__device__ int   g_cursor[MAX_NODES];        // fill cursors     (re-zeroed by scatter)
__device__ int   g_part[MAX_PARTS];          // scan block sums
__device__ int   g_partoff[MAX_PARTS];       // scanned block offsets
__device__ int2  g_sw[MAX_EDGES];            // CSR slots: (src, exp(e) bits)
__device__ int   g_scan_done;                // last-block detector (self-resetting)

// ---------------- packed f32x2 helpers --------------------------------------
__device__ __forceinline__ ull pack2(float lo, float hi) {
    ull r;
    asm("mov.b64 %0, {%1, %2};" : "=l"(r) : "f"(lo), "f"(hi));
    return r;
}
__device__ __forceinline__ void ffma2(ull& d, ull a, ull b) {
    asm("fma.rn.f32x2 %0, %1, %2, %0;" : "+l"(d) : "l"(a), "l"(b));
}
__device__ __forceinline__ float2 unpack2(ull v) {
    float lo, hi;
    asm("mov.b64 {%0, %1}, %2;" : "=f"(lo), "=f"(hi) : "l"(v));
    return make_float2(lo, hi);
}

// ---------------- kernel 1: tiled projection + degree histogram -------------
// Projection blocks: 256 threads, 256 nodes/block. Thread owns 4 nodes x 16
// output columns (8 f32x2 pairs). Each smem W load feeds 4 FFMA2 -> smem
// traffic /4 vs one-node-per-thread.
__global__ void __launch_bounds__(256)
proj_count_kernel(const float* __restrict__ feat,
                  const float* __restrict__ W,
                  const float* __restrict__ a,
                  const int* __restrict__ dst,
                  int n_nodes, int n_edges, int proj_blocks) {
    int tid = threadIdx.x;

    if ((int)blockIdx.x >= proj_blocks) {
        // -------- degree count blocks: 4 edges per thread via int4 ----------
        int t4 = ((int)blockIdx.x - proj_blocks) * 256 + tid;
        int base = t4 * 4;
        if (base + 3 < n_edges) {
            int4 d4 = reinterpret_cast<const int4*>(dst)[t4];
            atomicAdd(&g_cnt[d4.x], 1);
            atomicAdd(&g_cnt[d4.y], 1);
            atomicAdd(&g_cnt[d4.z], 1);
            atomicAdd(&g_cnt[d4.w], 1);
        } else {
            for (int t = base; t < n_edges; t++)
                atomicAdd(&g_cnt[dst[t]], 1);
        }
        return;
    }

    // -------- projection blocks ---------------------------------------------
    __shared__ ull   Ws2[IN_DIM * 32];   // [k][pair], 32 KB
    __shared__ float as[2 * OUT_DIM];

    const float4* W4 = reinterpret_cast<const float4*>(W);
    for (int i = tid; i < IN_DIM * OUT_DIM / 4; i += 256) {
        float4 w = W4[i];
        Ws2[2 * i]     = pack2(w.x, w.y);
        Ws2[2 * i + 1] = pack2(w.z, w.w);
    }
    if (tid < 2 * OUT_DIM) as[tid] = a[tid];
    __syncthreads();

    int jg = tid & 3;            // pair group: pairs jg*8 .. jg*8+7
    int n0 = blockIdx.x * 256 + (tid >> 2) * 4;

    ull acc[4][8];
#pragma unroll
    for (int i = 0; i < 4; i++)
#pragma unroll
        for (int p = 0; p < 8; p++) acc[i][p] = 0ull;

    const float4* frow[4];
#pragma unroll
    for (int i = 0; i < 4; i++) {
        int n = n0 + i;
        frow[i] = reinterpret_cast<const float4*>(
            feat + (size_t)((n < n_nodes) ? n : 0) * IN_DIM);
    }

    for (int k4 = 0; k4 < IN_DIM / 4; k4++) {
        float4 f[4];
#pragma unroll
        for (int i = 0; i < 4; i++) f[i] = frow[i][k4];
#pragma unroll
        for (int ks = 0; ks < 4; ks++) {
            int k = k4 * 4 + ks;
            ull wp[8];
#pragma unroll
            for (int p = 0; p < 8; p++) wp[p] = Ws2[k * 32 + jg * 8 + p];
#pragma unroll
            for (int i = 0; i < 4; i++) {
                float fv = (ks == 0) ? f[i].x : (ks == 1) ? f[i].y
                          : (ks == 2) ? f[i].z : f[i].w;
                ull fk = pack2(fv, fv);
#pragma unroll
                for (int p = 0; p < 8; p++) ffma2(acc[i][p], fk, wp[p]);
            }
        }
    }

    // az partials per node, reduced across the 4 jg lanes (adjacent lanes)
#pragma unroll
    for (int i = 0; i < 4; i++) {
        float s0 = 0.f, s1 = 0.f;
#pragma unroll
        for (int p = 0; p < 8; p++) {
            int col = (jg * 8 + p) * 2;
            float2 v = unpack2(acc[i][p]);
            s0 += v.x * as[col]           + v.y * as[col + 1];
            s1 += v.x * as[OUT_DIM + col] + v.y * as[OUT_DIM + col + 1];
        }
        s0 += __shfl_xor_sync(0xffffffffu, s0, 1);
        s0 += __shfl_xor_sync(0xffffffffu, s0, 2);
        s1 += __shfl_xor_sync(0xffffffffu, s1, 1);
        s1 += __shfl_xor_sync(0xffffffffu, s1, 2);
        int n = n0 + i;
        if (jg == 0 && n < n_nodes) {
            g_azs[n] = s0;
            g_azd[n] = s1;
        }
    }

    // z stores: each thread writes 64B contiguous per node (8 pairs)
    ull* z2 = reinterpret_cast<ull*>(g_z);
#pragma unroll
    for (int i = 0; i < 4; i++) {
        int n = n0 + i;
        if (n < n_nodes) {
            ull* dstp = z2 + (size_t)n * 32 + jg * 8;
#pragma unroll
            for (int p = 0; p < 8; p += 2) {
                longlong2 v;
                v.x = (long long)acc[i][p];
                v.y = (long long)acc[i][p + 1];
                *reinterpret_cast<longlong2*>(dstp + p) = v;
            }
        }
    }
}

// ---------------- kernel 2: scan (block scan + last-block part scan) --------
__global__ void __launch_bounds__(SCAN_BLK)
scan_kernel(int n, int nparts) {
    int tid = threadIdx.x;
    int i = blockIdx.x * SCAN_BLK + tid;
    int v = (i < n) ? g_cnt[i] : 0;

    int x = v;
#pragma unroll
    for (int o = 1; o < 32; o <<= 1) {
        int y = __shfl_up_sync(0xffffffffu, x, o);
        if ((tid & 31) >= o) x += y;
    }
    __shared__ int wsum[32];
    if ((tid & 31) == 31) wsum[tid >> 5] = x;
    __syncthreads();
    if (tid < 32) {
        int w = wsum[tid];
#pragma unroll
        for (int o = 1; o < 32; o <<= 1) {
            int y = __shfl_up_sync(0xffffffffu, w, o);
            if (tid >= o) w += y;
        }
        wsum[tid] = w;
    }
    __syncthreads();
    int warpoff = (tid >= 32) ? wsum[(tid >> 5) - 1] : 0;
    int incl = x + warpoff;
    if (i < n) g_off[i] = incl - v;
    if (tid == SCAN_BLK - 1) g_part[blockIdx.x] = incl;

    __shared__ int s_last;
    __threadfence();
    if (tid == 0) {
        int d = atomicAdd(&g_scan_done, 1);
        s_last = (d == (int)gridDim.x - 1) ? 1 : 0;
    }
    __syncthreads();
    if (s_last) {
        __threadfence();
        if (tid < 32) {
            int v0 = (tid < nparts) ? g_part[tid] : 0;
            int v1 = (tid + 32 < nparts) ? g_part[tid + 32] : 0;
            int x0 = v0;
#pragma unroll
            for (int o = 1; o < 32; o <<= 1) {
                int y = __shfl_up_sync(0xffffffffu, x0, o);
                if (tid >= o) x0 += y;
            }
            int tot0 = __shfl_sync(0xffffffffu, x0, 31);
            int x1 = v1;
#pragma unroll
            for (int o = 1; o < 32; o <<= 1) {
                int y = __shfl_up_sync(0xffffffffu, x1, o);
                if (tid >= o) x1 += y;
            }
            if (tid < nparts) g_partoff[tid] = x0 - v0;
            if (tid + 32 < nparts) g_partoff[tid + 32] = tot0 + x1 - v1;
        }
        if (tid == 0) g_scan_done = 0;   // reset for next replay
    }
}

// ---------------- kernel 3: edge weights + CSR fill --------------------------
__global__ void __launch_bounds__(256)
fill_kernel(const int* __restrict__ src,
            const int* __restrict__ dst,
            int n_edges) {
    int t = blockIdx.x * 256 + threadIdx.x;
    if (t >= n_edges) return;
    int s = src[t], d = dst[t];
    float e = g_azs[s] + g_azd[d];
    e = (e > 0.f) ? e : LEAKY * e;
    float w = __expf(e);   // e bounded (|e| small), exp safe without max-shift
    int pos = g_off[d] + g_partoff[d >> 10] + atomicAdd(&g_cursor[d], 1);
    g_sw[pos] = make_int2(s, __float_as_int(w));
}

// ---------------- kernel 4: one warp per destination node --------------------
// (src, w) read as warp-uniform LDG.64 broadcast; no shuffles. unroll 8 for MLP.
__global__ void __launch_bounds__(256)
scatter_kernel(float* __restrict__ h, int n_nodes) {
    int warp_id = (blockIdx.x * 256 + threadIdx.x) >> 5;
    int lane = threadIdx.x & 31;
    if (warp_id >= n_nodes) return;
    int node = warp_id;

    int start = g_off[node] + g_partoff[node >> 10];
    int cnt = g_cnt[node];

    const ull* z2 = reinterpret_cast<const ull*>(g_z);
    const int2* sw = g_sw + start;

    ull acc = 0ull;
    float wsum = 0.f;

#pragma unroll 8
    for (int j = 0; j < cnt; j++) {
        int2 e = __ldg(sw + j);                      // uniform broadcast
        float ww = __int_as_float(e.y);
        wsum += ww;
        ffma2(acc, pack2(ww, ww), z2[(size_t)e.x * 32 + lane]);
    }

    float inv = (cnt > 0) ? 1.f / wsum : 0.f;
    float2 v = unpack2(acc);
    float2* out = reinterpret_cast<float2*>(h + (size_t)node * OUT_DIM);
    out[lane] = make_float2(v.x * inv, v.y * inv);

    if (lane == 0) {          // restore invariant for next replay
        g_cnt[node] = 0;
        g_cursor[node] = 0;
    }
}

// ---------------- launch ------------------------------------------------------
extern "C" void kernel_launch(void* const* d_in, const int* in_sizes, int n_in,
                              void* d_out, int out_size) {
    const float* feat = (const float*)d_in[0];
    const int*   src  = (const int*)  d_in[1];
    const int*   dst  = (const int*)  d_in[2];
    const float* W    = (const float*)d_in[3];
    const float* a    = (const float*)d_in[4];
    float* h = (float*)d_out;

    int n_nodes = in_sizes[0] / IN_DIM;
    int n_edges = in_sizes[1];
    int nparts = (n_nodes + SCAN_BLK - 1) / SCAN_BLK;

    int proj_blocks  = (n_nodes + 255) / 256;
    int count_blocks = (n_edges + 1023) / 1024;   // 4 edges/thread, 256 threads
    proj_count_kernel<<<proj_blocks + count_blocks, 256>>>(
        feat, W, a, dst, n_nodes, n_edges, proj_blocks);

    scan_kernel<<<nparts, SCAN_BLK>>>(n_nodes, nparts);

    fill_kernel<<<(n_edges + 255) / 256, 256>>>(src, dst, n_edges);

    {
        int blocks = (n_nodes + 7) / 8;   // 8 warps/block
        scatter_kernel<<<blocks, 256>>>(h, n_nodes);
    }
}

// round 5
// speedup vs baseline: 1.1502x; 1.0660x over previous
#include <cuda_runtime.h>
#include <cuda_bf16.h>
#include <cstdint>

#define MAX_NODES 50048
#define MAX_EDGES 800000
#define IN_DIM    128
#define OUT_DIM   64
#define LEAKY     0.01f
#define SCAN_BLK  1024
#define MAX_PARTS ((MAX_NODES + SCAN_BLK - 1) / SCAN_BLK)

typedef unsigned long long ull;

// ---------------- scratch (device globals; zero-initialized at load) -------
__device__ float g_z[MAX_NODES * OUT_DIM];   // projected features
__device__ float g_azs[MAX_NODES];           // z . a[:64]
__device__ float g_azd[MAX_NODES];           // z . a[64:]
__device__ int   g_cnt[MAX_NODES];           // per-dst degree (re-zeroed by scatter)
__device__ int   g_off[MAX_NODES];           // block-local excl offset; fill bumps it
__device__ int   g_part[MAX_PARTS];          // scan block sums
__device__ int   g_partoff[MAX_PARTS];       // scanned block offsets
__device__ int2  g_sw[MAX_EDGES];            // CSR slots: (src, exp(e) bits)
__device__ int   g_scan_done;                // last-block detector (self-resetting)

// ---------------- packed f32x2 helpers --------------------------------------
__device__ __forceinline__ ull pack2(float lo, float hi) {
    ull r;
    asm("mov.b64 %0, {%1, %2};" : "=l"(r) : "f"(lo), "f"(hi));
    return r;
}
__device__ __forceinline__ void ffma2(ull& d, ull a, ull b) {
    asm("fma.rn.f32x2 %0, %1, %2, %0;" : "+l"(d) : "l"(a), "l"(b));
}
__device__ __forceinline__ float2 unpack2(ull v) {
    float lo, hi;
    asm("mov.b64 {%0, %1}, %2;" : "=f"(lo), "=f"(hi) : "l"(v));
    return make_float2(lo, hi);
}

// ---------------- kernel 1: tiled projection + degree histogram -------------
__global__ void __launch_bounds__(256)
proj_count_kernel(const float* __restrict__ feat,
                  const float* __restrict__ W,
                  const float* __restrict__ a,
                  const int* __restrict__ dst,
                  int n_nodes, int n_edges, int proj_blocks) {
    int tid = threadIdx.x;

    if ((int)blockIdx.x >= proj_blocks) {
        int t4 = ((int)blockIdx.x - proj_blocks) * 256 + tid;
        int base = t4 * 4;
        if (base + 3 < n_edges) {
            int4 d4 = reinterpret_cast<const int4*>(dst)[t4];
            atomicAdd(&g_cnt[d4.x], 1);
            atomicAdd(&g_cnt[d4.y], 1);
            atomicAdd(&g_cnt[d4.z], 1);
            atomicAdd(&g_cnt[d4.w], 1);
        } else {
            for (int t = base; t < n_edges; t++)
                atomicAdd(&g_cnt[dst[t]], 1);
        }
        return;
    }

    __shared__ ull   Ws2[IN_DIM * 32];   // [k][pair], 32 KB
    __shared__ float as[2 * OUT_DIM];

    const float4* W4 = reinterpret_cast<const float4*>(W);
    for (int i = tid; i < IN_DIM * OUT_DIM / 4; i += 256) {
        float4 w = W4[i];
        Ws2[2 * i]     = pack2(w.x, w.y);
        Ws2[2 * i + 1] = pack2(w.z, w.w);
    }
    if (tid < 2 * OUT_DIM) as[tid] = a[tid];
    __syncthreads();

    int jg = tid & 3;            // pair group: pairs jg*8 .. jg*8+7
    int n0 = blockIdx.x * 256 + (tid >> 2) * 4;

    ull acc[4][8];
#pragma unroll
    for (int i = 0; i < 4; i++)
#pragma unroll
        for (int p = 0; p < 8; p++) acc[i][p] = 0ull;

    const float4* frow[4];
#pragma unroll
    for (int i = 0; i < 4; i++) {
        int n = n0 + i;
        frow[i] = reinterpret_cast<const float4*>(
            feat + (size_t)((n < n_nodes) ? n : 0) * IN_DIM);
    }

    for (int k4 = 0; k4 < IN_DIM / 4; k4++) {
        float4 f[4];
#pragma unroll
        for (int i = 0; i < 4; i++) f[i] = frow[i][k4];
#pragma unroll
        for (int ks = 0; ks < 4; ks++) {
            int k = k4 * 4 + ks;
            ull wp[8];
#pragma unroll
            for (int p = 0; p < 8; p++) wp[p] = Ws2[k * 32 + jg * 8 + p];
#pragma unroll
            for (int i = 0; i < 4; i++) {
                float fv = (ks == 0) ? f[i].x : (ks == 1) ? f[i].y
                          : (ks == 2) ? f[i].z : f[i].w;
                ull fk = pack2(fv, fv);
#pragma unroll
                for (int p = 0; p < 8; p++) ffma2(acc[i][p], fk, wp[p]);
            }
        }
    }

#pragma unroll
    for (int i = 0; i < 4; i++) {
        float s0 = 0.f, s1 = 0.f;
#pragma unroll
        for (int p = 0; p < 8; p++) {
            int col = (jg * 8 + p) * 2;
            float2 v = unpack2(acc[i][p]);
            s0 += v.x * as[col]           + v.y * as[col + 1];
            s1 += v.x * as[OUT_DIM + col] + v.y * as[OUT_DIM + col + 1];
        }
        s0 += __shfl_xor_sync(0xffffffffu, s0, 1);
        s0 += __shfl_xor_sync(0xffffffffu, s0, 2);
        s1 += __shfl_xor_sync(0xffffffffu, s1, 1);
        s1 += __shfl_xor_sync(0xffffffffu, s1, 2);
        int n = n0 + i;
        if (jg == 0 && n < n_nodes) {
            g_azs[n] = s0;
            g_azd[n] = s1;
        }
    }

    ull* z2 = reinterpret_cast<ull*>(g_z);
#pragma unroll
    for (int i = 0; i < 4; i++) {
        int n = n0 + i;
        if (n < n_nodes) {
            ull* dstp = z2 + (size_t)n * 32 + jg * 8;
#pragma unroll
            for (int p = 0; p < 8; p += 2) {
                longlong2 v;
                v.x = (long long)acc[i][p];
                v.y = (long long)acc[i][p + 1];
                *reinterpret_cast<longlong2*>(dstp + p) = v;
            }
        }
    }
}

// ---------------- kernel 2: scan (block scan + last-block part scan) --------
__global__ void __launch_bounds__(SCAN_BLK)
scan_kernel(int n, int nparts) {
    int tid = threadIdx.x;
    int i = blockIdx.x * SCAN_BLK + tid;
    int v = (i < n) ? g_cnt[i] : 0;

    int x = v;
#pragma unroll
    for (int o = 1; o < 32; o <<= 1) {
        int y = __shfl_up_sync(0xffffffffu, x, o);
        if ((tid & 31) >= o) x += y;
    }
    __shared__ int wsum[32];
    if ((tid & 31) == 31) wsum[tid >> 5] = x;
    __syncthreads();
    if (tid < 32) {
        int w = wsum[tid];
#pragma unroll
        for (int o = 1; o < 32; o <<= 1) {
            int y = __shfl_up_sync(0xffffffffu, w, o);
            if (tid >= o) w += y;
        }
        wsum[tid] = w;
    }
    __syncthreads();
    int warpoff = (tid >= 32) ? wsum[(tid >> 5) - 1] : 0;
    int incl = x + warpoff;
    if (i < n) g_off[i] = incl - v;
    if (tid == SCAN_BLK - 1) g_part[blockIdx.x] = incl;

    __shared__ int s_last;
    __threadfence();
    if (tid == 0) {
        int d = atomicAdd(&g_scan_done, 1);
        s_last = (d == (int)gridDim.x - 1) ? 1 : 0;
    }
    __syncthreads();
    if (s_last) {
        __threadfence();
        if (tid < 32) {
            int v0 = (tid < nparts) ? g_part[tid] : 0;
            int v1 = (tid + 32 < nparts) ? g_part[tid + 32] : 0;
            int x0 = v0;
#pragma unroll
            for (int o = 1; o < 32; o <<= 1) {
                int y = __shfl_up_sync(0xffffffffu, x0, o);
                if (tid >= o) x0 += y;
            }
            int tot0 = __shfl_sync(0xffffffffu, x0, 31);
            int x1 = v1;
#pragma unroll
            for (int o = 1; o < 32; o <<= 1) {
                int y = __shfl_up_sync(0xffffffffu, x1, o);
                if (tid >= o) x1 += y;
            }
            if (tid < nparts) g_partoff[tid] = x0 - v0;
            if (tid + 32 < nparts) g_partoff[tid + 32] = tot0 + x1 - v1;
        }
        if (tid == 0) g_scan_done = 0;   // reset for next replay
    }
}

// ---------------- kernel 3: edge weights + CSR fill --------------------------
// cursor == g_off itself (scan rewrites it each replay)
__global__ void __launch_bounds__(256)
fill_kernel(const int* __restrict__ src,
            const int* __restrict__ dst,
            int n_edges) {
    int t = blockIdx.x * 256 + threadIdx.x;
    if (t >= n_edges) return;
    int s = src[t], d = dst[t];
    float e = g_azs[s] + g_azd[d];
    e = (e > 0.f) ? e : LEAKY * e;
    float w = __expf(e);   // e bounded, exp safe without max-shift
    int pos = g_partoff[d >> 10] + atomicAdd(&g_off[d], 1);
    g_sw[pos] = make_int2(s, __float_as_int(w));
}

// ---------------- kernel 4: one warp per destination node --------------------
// Explicit 8-deep software batching: 8 sw loads, then 8 z gathers, then math.
#define SBATCH 8
__global__ void __launch_bounds__(256)
scatter_kernel(float* __restrict__ h, int n_nodes) {
    int warp_id = (blockIdx.x * 256 + threadIdx.x) >> 5;
    int lane = threadIdx.x & 31;
    if (warp_id >= n_nodes) return;
    int node = warp_id;

    int cnt = g_cnt[node];
    // after fill, g_off[node] = local_excl + cnt
    int start = g_partoff[node >> 10] + g_off[node] - cnt;

    const ull* z2 = reinterpret_cast<const ull*>(g_z) + lane;
    const int2* sw = g_sw + start;

    ull acc = 0ull;
    float wsum = 0.f;

    for (int base = 0; base < cnt; base += SBATCH) {
        int m = cnt - base;
        int2 e[SBATCH];
#pragma unroll
        for (int j = 0; j < SBATCH; j++)
            e[j] = (j < m) ? __ldg(sw + base + j) : make_int2(0, 0);
        ull zv[SBATCH];
#pragma unroll
        for (int j = 0; j < SBATCH; j++)
            zv[j] = z2[(size_t)e[j].x * 32];
#pragma unroll
        for (int j = 0; j < SBATCH; j++) {
            float w = __int_as_float(e[j].y);
            wsum += w;
            ffma2(acc, pack2(w, w), zv[j]);
        }
    }

    float inv = (cnt > 0) ? 1.f / wsum : 0.f;
    float2 v = unpack2(acc);
    float2* out = reinterpret_cast<float2*>(h + (size_t)node * OUT_DIM);
    out[lane] = make_float2(v.x * inv, v.y * inv);

    if (lane == 0) g_cnt[node] = 0;   // restore invariant for next replay
}

// ---------------- launch ------------------------------------------------------
extern "C" void kernel_launch(void* const* d_in, const int* in_sizes, int n_in,
                              void* d_out, int out_size) {
    const float* feat = (const float*)d_in[0];
    const int*   src  = (const int*)  d_in[1];
    const int*   dst  = (const int*)  d_in[2];
    const float* W    = (const float*)d_in[3];
    const float* a    = (const float*)d_in[4];
    float* h = (float*)d_out;

    int n_nodes = in_sizes[0] / IN_DIM;
    int n_edges = in_sizes[1];
    int nparts = (n_nodes + SCAN_BLK - 1) / SCAN_BLK;

    int proj_blocks  = (n_nodes + 255) / 256;
    int count_blocks = (n_edges + 1023) / 1024;
    proj_count_kernel<<<proj_blocks + count_blocks, 256>>>(
        feat, W, a, dst, n_nodes, n_edges, proj_blocks);

    scan_kernel<<<nparts, SCAN_BLK>>>(n_nodes, nparts);

    fill_kernel<<<(n_edges + 255) / 256, 256>>>(src, dst, n_edges);

    {
        int blocks = (n_nodes + 7) / 8;   // 8 warps/block
        scatter_kernel<<<blocks, 256>>>(h, n_nodes);
    }
}